// round 15
// baseline (speedup 1.0000x reference)
#include <cuda_runtime.h>
#include <cstdint>

#define S_LEN 2048
#define BATCH 64
#define HIDD  512

// ---------------- scratch (device globals; no allocations allowed) ----------
__device__ float g_XB[S_LEN * BATCH * HIDD];   // precomputed input term of current layer
__device__ float g_Y [S_LEN * BATCH * HIDD];   // layer-0 outputs (input to layer-1 GEMM)
__device__ float g_Wt[2 * HIDD * HIDD];        // W_ih transposed: [layer][k][n]
__device__ float g_bias[2 * HIDD];             // b_ih + b_hh

// ---------------- prep: transpose W_ih, fold biases --------------------------
__global__ void prep_kernel(const float* __restrict__ W_ih,
                            const float* __restrict__ b_ih,
                            const float* __restrict__ b_hh) {
    const int n = blockIdx.x;      // 0..511 (output col)
    const int l = blockIdx.y;      // layer
    const int k = threadIdx.x;     // 0..511
    g_Wt[((size_t)l * HIDD + k) * HIDD + n] = W_ih[((size_t)l * HIDD + n) * HIDD + k];
    if (n == 0) g_bias[l * HIDD + k] = b_ih[l * HIDD + k] + b_hh[l * HIDD + k];
}

// ---------------- input GEMM: XB[s,b,:] = A_row @ Wt + bias ------------------
__global__ __launch_bounds__(256) void xb_gemm(const int* __restrict__ src,
                                               const float* __restrict__ embed,
                                               int layer) {
    __shared__ float As[64][33];
    __shared__ float Ws[32][64];
    __shared__ const float* Arow[64];

    const int s   = blockIdx.y;
    const int n0  = blockIdx.x * 64;
    const int tid = threadIdx.x;
    const float* Wt = g_Wt + (size_t)layer * HIDD * HIDD;

    if (tid < 64) {
        if (src) Arow[tid] = embed + (size_t)src[tid * S_LEN + s] * HIDD;
        else     Arow[tid] = g_Y + ((size_t)s * BATCH + tid) * HIDD;
    }
    __syncthreads();

    const int tx = tid & 15, ty = tid >> 4;
    const int la_b = tid >> 3, la_k = (tid & 7) * 4;
    const int lw_k = tid >> 4, lw_n = (tid & 15) * 4;

    float acc[4][4] = {};

#pragma unroll 1
    for (int k0 = 0; k0 < HIDD; k0 += 32) {
        float4 a0 = *(const float4*)(Arow[la_b]      + k0 + la_k);
        float4 a1 = *(const float4*)(Arow[la_b + 32] + k0 + la_k);
        float4 w0 = *(const float4*)(Wt + (size_t)(k0 + lw_k)      * HIDD + n0 + lw_n);
        float4 w1 = *(const float4*)(Wt + (size_t)(k0 + lw_k + 16) * HIDD + n0 + lw_n);
        __syncthreads();
        As[la_b][la_k + 0] = a0.x; As[la_b][la_k + 1] = a0.y;
        As[la_b][la_k + 2] = a0.z; As[la_b][la_k + 3] = a0.w;
        As[la_b + 32][la_k + 0] = a1.x; As[la_b + 32][la_k + 1] = a1.y;
        As[la_b + 32][la_k + 2] = a1.z; As[la_b + 32][la_k + 3] = a1.w;
        *(float4*)&Ws[lw_k][lw_n]      = w0;
        *(float4*)&Ws[lw_k + 16][lw_n] = w1;
        __syncthreads();
#pragma unroll
        for (int k = 0; k < 32; ++k) {
            float4 w = *(const float4*)&Ws[k][tx * 4];
            float a0_ = As[ty * 4 + 0][k];
            float a1_ = As[ty * 4 + 1][k];
            float a2_ = As[ty * 4 + 2][k];
            float a3_ = As[ty * 4 + 3][k];
            acc[0][0] += a0_ * w.x; acc[0][1] += a0_ * w.y; acc[0][2] += a0_ * w.z; acc[0][3] += a0_ * w.w;
            acc[1][0] += a1_ * w.x; acc[1][1] += a1_ * w.y; acc[1][2] += a1_ * w.z; acc[1][3] += a1_ * w.w;
            acc[2][0] += a2_ * w.x; acc[2][1] += a2_ * w.y; acc[2][2] += a2_ * w.z; acc[2][3] += a2_ * w.w;
            acc[3][0] += a3_ * w.x; acc[3][1] += a3_ * w.y; acc[3][2] += a3_ * w.z; acc[3][3] += a3_ * w.w;
        }
    }

    const float4 bv = *(const float4*)(g_bias + layer * HIDD + n0 + tx * 4);
#pragma unroll
    for (int i = 0; i < 4; ++i) {
        int row = s * BATCH + ty * 4 + i;
        float4 o = make_float4(acc[i][0] + bv.x, acc[i][1] + bv.y,
                               acc[i][2] + bv.z, acc[i][3] + bv.w);
        *(float4*)(g_XB + (size_t)row * HIDD + n0 + tx * 4) = o;
    }
}

// ---------------- sequential recurrence: batch-split cluster scan ------------
// Batch rows are independent -> NO grid-wide sync needed.
// 16 clusters of 8 CTAs; cluster owns 4 batch rows; CTA rank owns 64 output
// cols with its W_hh slice resident in SMEM (128 KB). Each thread computes one
// (row,col) output (512 MACs, no reduction), pushes it to all 8 peers' H
// buffers via DSMEM, then one cluster barrier per step.

#define W_PITCH 516            // 516 % 32 == 4 -> conflict-free strided rows
#define H_PITCH 516
#define SCAN_SMEM ((64 * W_PITCH + 2 * 4 * H_PITCH) * 4)

__device__ __forceinline__ void cluster_arrive_wait() {
    asm volatile("barrier.cluster.arrive.aligned;" ::: "memory");
    asm volatile("barrier.cluster.wait.aligned;"  ::: "memory");
}

extern "C" __global__ void __launch_bounds__(256, 1) __cluster_dims__(8, 1, 1)
rnn_scan2(const float* __restrict__ W_hh, int layer, float* __restrict__ out) {
    extern __shared__ float smem[];
    float* Wc = smem;                      // [64][W_PITCH], Wc[c][k] = W_hh[col0+c][k]
    float* Hs = smem + 64 * W_PITCH;       // [2][4][H_PITCH] double-buffered hidden

    const int tid  = threadIdx.x;
    const int rank = blockIdx.x & 7;           // cluster cta rank
    const int r0   = (blockIdx.x >> 3) * 4;    // first batch row of this cluster
    const int lane = tid & 31;
    const int c    = (tid >> 5) * 8 + (lane >> 2);  // local col 0..63
    const int r    = lane & 3;                       // local row 0..3
    const int col  = rank * 64 + c;                  // global hidden col
    const int b    = r0 + r;                         // batch row

    const float* Whh = W_hh + (size_t)layer * HIDD * HIDD;

    // load W slice (cols [rank*64, +64), all k)
    for (int i = tid; i < 64 * HIDD; i += 256) {
        int cc = i >> 9, k = i & 511;
        Wc[cc * W_PITCH + k] = Whh[(size_t)(rank * 64 + cc) * HIDD + k];
    }
    // zero both H buffers (t=0 reads buf 0 == h_0 = 0)
    for (int i = tid; i < 2 * 4 * H_PITCH; i += 256) Hs[i] = 0.f;

    // precompute DSMEM peer addresses of my output slot, both buffers
    uint32_t hbase = (uint32_t)__cvta_generic_to_shared(Hs);
    uint32_t off0 = hbase + (uint32_t)((r * H_PITCH + col) * 4);
    uint32_t off1 = off0 + (uint32_t)(4 * H_PITCH * 4);
    uint32_t pa0[8], pa1[8];
#pragma unroll
    for (int j = 0; j < 8; ++j) {
        asm volatile("mapa.shared::cluster.u32 %0, %1, %2;" : "=r"(pa0[j]) : "r"(off0), "r"(j));
        asm volatile("mapa.shared::cluster.u32 %0, %1, %2;" : "=r"(pa1[j]) : "r"(off1), "r"(j));
    }

    cluster_arrive_wait();   // H zeroed everywhere before anyone pushes

    const float* XBp = g_XB + (size_t)b * HIDD + col;
    float* Yp = (layer == 0) ? (g_Y + (size_t)b * HIDD + col) : nullptr;
    const float* wrow = Wc + c * W_PITCH;
    float lastv = 0.f;

    for (int t = 0; t < S_LEN; ++t) {
        const int rb = t & 1;
        float xb = XBp[(size_t)t * (BATCH * HIDD)];   // LDG issued early, hidden by dot

        const float* hrow = Hs + rb * (4 * H_PITCH) + r * H_PITCH;
        float acc = 0.f;
#pragma unroll 16
        for (int k = 0; k < HIDD; k += 4) {
            float4 hv = *(const float4*)(hrow + k);
            float4 wv = *(const float4*)(wrow + k);
            acc += hv.x * wv.x;
            acc += hv.y * wv.y;
            acc += hv.z * wv.z;
            acc += hv.w * wv.w;
        }

        float v = tanhf(xb + acc);
        lastv = v;

        // push my value into all 8 CTAs' write buffer
        if (rb) {
#pragma unroll
            for (int j = 0; j < 8; ++j)
                asm volatile("st.shared::cluster.f32 [%0], %1;" :: "r"(pa0[j]), "f"(v) : "memory");
        } else {
#pragma unroll
            for (int j = 0; j < 8; ++j)
                asm volatile("st.shared::cluster.f32 [%0], %1;" :: "r"(pa1[j]), "f"(v) : "memory");
        }
        if (Yp) Yp[(size_t)t * (BATCH * HIDD)] = v;

        cluster_arrive_wait();   // publish pushes; also guards buffer reuse
    }

    out[(size_t)layer * BATCH * HIDD + (size_t)b * HIDD + col] = lastv;
}

// ---------------- launch ------------------------------------------------------
extern "C" void kernel_launch(void* const* d_in, const int* in_sizes, int n_in,
                              void* d_out, int out_size) {
    const int*   src   = (const int*)  d_in[0];   // [64][2048] int32
    const float* embed = (const float*)d_in[1];   // [32000][512]
    const float* W_ih  = (const float*)d_in[2];   // [2][512][512]
    const float* W_hh  = (const float*)d_in[3];   // [2][512][512]
    const float* b_ih  = (const float*)d_in[4];   // [2][512]
    const float* b_hh  = (const float*)d_in[5];   // [2][512]
    float* out = (float*)d_out;                   // [2][64][512]

    static bool attr_done = false;
    if (!attr_done) {
        cudaFuncSetAttribute(rnn_scan2, cudaFuncAttributeMaxDynamicSharedMemorySize, SCAN_SMEM);
        attr_done = true;
    }

    prep_kernel<<<dim3(HIDD, 2), HIDD>>>(W_ih, b_ih, b_hh);

    // layer 0
    xb_gemm<<<dim3(8, S_LEN), 256>>>(src, embed, 0);
    rnn_scan2<<<128, 256, SCAN_SMEM>>>(W_hh, 0, out);

    // layer 1 (input = layer-0 outputs in g_Y)
    xb_gemm<<<dim3(8, S_LEN), 256>>>(nullptr, embed, 1);
    rnn_scan2<<<128, 256, SCAN_SMEM>>>(W_hh, 1, out);
}

// round 16
// speedup vs baseline: 1.0012x; 1.0012x over previous
#include <cuda_runtime.h>
#include <cstdint>

#define S_LEN 2048
#define BATCH 64
#define HIDD  512

// ---------------- scratch (device globals; no allocations allowed) ----------
__device__ float g_XB[S_LEN * BATCH * HIDD];   // precomputed input term of current layer
__device__ float g_Y [S_LEN * BATCH * HIDD];   // layer-0 outputs (input to layer-1 GEMM)
__device__ float g_Wt[2 * HIDD * HIDD];        // W_ih transposed: [layer][k][n]
__device__ float g_bias[2 * HIDD];             // b_ih + b_hh

// ---------------- prep: transpose W_ih, fold biases --------------------------
__global__ void prep_kernel(const float* __restrict__ W_ih,
                            const float* __restrict__ b_ih,
                            const float* __restrict__ b_hh) {
    const int n = blockIdx.x;      // 0..511 (output col)
    const int l = blockIdx.y;      // layer
    const int k = threadIdx.x;     // 0..511
    g_Wt[((size_t)l * HIDD + k) * HIDD + n] = W_ih[((size_t)l * HIDD + n) * HIDD + k];
    if (n == 0) g_bias[l * HIDD + k] = b_ih[l * HIDD + k] + b_hh[l * HIDD + k];
}

// ---------------- input GEMM: XB[s,b,:] = A_row @ Wt + bias ------------------
__global__ __launch_bounds__(256) void xb_gemm(const int* __restrict__ src,
                                               const float* __restrict__ embed,
                                               int layer) {
    __shared__ float As[64][33];
    __shared__ float Ws[32][64];
    __shared__ const float* Arow[64];

    const int s   = blockIdx.y;
    const int n0  = blockIdx.x * 64;
    const int tid = threadIdx.x;
    const float* Wt = g_Wt + (size_t)layer * HIDD * HIDD;

    if (tid < 64) {
        if (src) Arow[tid] = embed + (size_t)src[tid * S_LEN + s] * HIDD;
        else     Arow[tid] = g_Y + ((size_t)s * BATCH + tid) * HIDD;
    }
    __syncthreads();

    const int tx = tid & 15, ty = tid >> 4;
    const int la_b = tid >> 3, la_k = (tid & 7) * 4;
    const int lw_k = tid >> 4, lw_n = (tid & 15) * 4;

    float acc[4][4] = {};

#pragma unroll 1
    for (int k0 = 0; k0 < HIDD; k0 += 32) {
        float4 a0 = *(const float4*)(Arow[la_b]      + k0 + la_k);
        float4 a1 = *(const float4*)(Arow[la_b + 32] + k0 + la_k);
        float4 w0 = *(const float4*)(Wt + (size_t)(k0 + lw_k)      * HIDD + n0 + lw_n);
        float4 w1 = *(const float4*)(Wt + (size_t)(k0 + lw_k + 16) * HIDD + n0 + lw_n);
        __syncthreads();
        As[la_b][la_k + 0] = a0.x; As[la_b][la_k + 1] = a0.y;
        As[la_b][la_k + 2] = a0.z; As[la_b][la_k + 3] = a0.w;
        As[la_b + 32][la_k + 0] = a1.x; As[la_b + 32][la_k + 1] = a1.y;
        As[la_b + 32][la_k + 2] = a1.z; As[la_b + 32][la_k + 3] = a1.w;
        *(float4*)&Ws[lw_k][lw_n]      = w0;
        *(float4*)&Ws[lw_k + 16][lw_n] = w1;
        __syncthreads();
#pragma unroll
        for (int k = 0; k < 32; ++k) {
            float4 w = *(const float4*)&Ws[k][tx * 4];
            float a0_ = As[ty * 4 + 0][k];
            float a1_ = As[ty * 4 + 1][k];
            float a2_ = As[ty * 4 + 2][k];
            float a3_ = As[ty * 4 + 3][k];
            acc[0][0] += a0_ * w.x; acc[0][1] += a0_ * w.y; acc[0][2] += a0_ * w.z; acc[0][3] += a0_ * w.w;
            acc[1][0] += a1_ * w.x; acc[1][1] += a1_ * w.y; acc[1][2] += a1_ * w.z; acc[1][3] += a1_ * w.w;
            acc[2][0] += a2_ * w.x; acc[2][1] += a2_ * w.y; acc[2][2] += a2_ * w.z; acc[2][3] += a2_ * w.w;
            acc[3][0] += a3_ * w.x; acc[3][1] += a3_ * w.y; acc[3][2] += a3_ * w.z; acc[3][3] += a3_ * w.w;
        }
    }

    const float4 bv = *(const float4*)(g_bias + layer * HIDD + n0 + tx * 4);
#pragma unroll
    for (int i = 0; i < 4; ++i) {
        int row = s * BATCH + ty * 4 + i;
        float4 o = make_float4(acc[i][0] + bv.x, acc[i][1] + bv.y,
                               acc[i][2] + bv.z, acc[i][3] + bv.w);
        *(float4*)(g_XB + (size_t)row * HIDD + n0 + tx * 4) = o;
    }
}

// ---------------- sequential recurrence: batch-split cluster scan ------------
// Batch rows are independent -> NO grid-wide sync needed.
// 16 clusters of 8 CTAs; cluster owns 4 batch rows; CTA rank owns 64 output
// cols with its W_hh slice resident in SMEM (128 KB). Each thread computes one
// (row,col) output (512 MACs, no reduction), pushes it to all 8 peers' H
// buffers via DSMEM, then one cluster barrier per step.

#define W_PITCH 516            // 516 % 32 == 4 -> conflict-free strided rows
#define H_PITCH 516
#define SCAN_SMEM ((64 * W_PITCH + 2 * 4 * H_PITCH) * 4)

__device__ __forceinline__ void cluster_arrive_wait() {
    asm volatile("barrier.cluster.arrive.aligned;" ::: "memory");
    asm volatile("barrier.cluster.wait.aligned;"  ::: "memory");
}

extern "C" __global__ void __launch_bounds__(256, 1) __cluster_dims__(8, 1, 1)
rnn_scan2(const float* __restrict__ W_hh, int layer, float* __restrict__ out) {
    extern __shared__ float smem[];
    float* Wc = smem;                      // [64][W_PITCH], Wc[c][k] = W_hh[col0+c][k]
    float* Hs = smem + 64 * W_PITCH;       // [2][4][H_PITCH] double-buffered hidden

    const int tid  = threadIdx.x;
    const int rank = blockIdx.x & 7;           // cluster cta rank
    const int r0   = (blockIdx.x >> 3) * 4;    // first batch row of this cluster
    const int lane = tid & 31;
    const int c    = (tid >> 5) * 8 + (lane >> 2);  // local col 0..63
    const int r    = lane & 3;                       // local row 0..3
    const int col  = rank * 64 + c;                  // global hidden col
    const int b    = r0 + r;                         // batch row

    const float* Whh = W_hh + (size_t)layer * HIDD * HIDD;

    // load W slice (cols [rank*64, +64), all k)
    for (int i = tid; i < 64 * HIDD; i += 256) {
        int cc = i >> 9, k = i & 511;
        Wc[cc * W_PITCH + k] = Whh[(size_t)(rank * 64 + cc) * HIDD + k];
    }
    // zero both H buffers (t=0 reads buf 0 == h_0 = 0)
    for (int i = tid; i < 2 * 4 * H_PITCH; i += 256) Hs[i] = 0.f;

    // precompute DSMEM peer addresses of my output slot, both buffers
    uint32_t hbase = (uint32_t)__cvta_generic_to_shared(Hs);
    uint32_t off0 = hbase + (uint32_t)((r * H_PITCH + col) * 4);
    uint32_t off1 = off0 + (uint32_t)(4 * H_PITCH * 4);
    uint32_t pa0[8], pa1[8];
#pragma unroll
    for (int j = 0; j < 8; ++j) {
        asm volatile("mapa.shared::cluster.u32 %0, %1, %2;" : "=r"(pa0[j]) : "r"(off0), "r"(j));
        asm volatile("mapa.shared::cluster.u32 %0, %1, %2;" : "=r"(pa1[j]) : "r"(off1), "r"(j));
    }

    cluster_arrive_wait();   // H zeroed everywhere before anyone pushes

    const float* XBp = g_XB + (size_t)b * HIDD + col;
    float* Yp = (layer == 0) ? (g_Y + (size_t)b * HIDD + col) : nullptr;
    const float* wrow = Wc + c * W_PITCH;
    float lastv = 0.f;

    for (int t = 0; t < S_LEN; ++t) {
        const int rb = t & 1;
        float xb = XBp[(size_t)t * (BATCH * HIDD)];   // LDG issued early, hidden by dot

        const float* hrow = Hs + rb * (4 * H_PITCH) + r * H_PITCH;
        float acc = 0.f;
#pragma unroll 16
        for (int k = 0; k < HIDD; k += 4) {
            float4 hv = *(const float4*)(hrow + k);
            float4 wv = *(const float4*)(wrow + k);
            acc += hv.x * wv.x;
            acc += hv.y * wv.y;
            acc += hv.z * wv.z;
            acc += hv.w * wv.w;
        }

        float v = tanhf(xb + acc);
        lastv = v;

        // push my value into all 8 CTAs' write buffer
        if (rb) {
#pragma unroll
            for (int j = 0; j < 8; ++j)
                asm volatile("st.shared::cluster.f32 [%0], %1;" :: "r"(pa0[j]), "f"(v) : "memory");
        } else {
#pragma unroll
            for (int j = 0; j < 8; ++j)
                asm volatile("st.shared::cluster.f32 [%0], %1;" :: "r"(pa1[j]), "f"(v) : "memory");
        }
        if (Yp) Yp[(size_t)t * (BATCH * HIDD)] = v;

        cluster_arrive_wait();   // publish pushes; also guards buffer reuse
    }

    out[(size_t)layer * BATCH * HIDD + (size_t)b * HIDD + col] = lastv;
}

// ---------------- launch ------------------------------------------------------
extern "C" void kernel_launch(void* const* d_in, const int* in_sizes, int n_in,
                              void* d_out, int out_size) {
    const int*   src   = (const int*)  d_in[0];   // [64][2048] int32
    const float* embed = (const float*)d_in[1];   // [32000][512]
    const float* W_ih  = (const float*)d_in[2];   // [2][512][512]
    const float* W_hh  = (const float*)d_in[3];   // [2][512][512]
    const float* b_ih  = (const float*)d_in[4];   // [2][512]
    const float* b_hh  = (const float*)d_in[5];   // [2][512]
    float* out = (float*)d_out;                   // [2][64][512]

    static bool attr_done = false;
    if (!attr_done) {
        cudaFuncSetAttribute(rnn_scan2, cudaFuncAttributeMaxDynamicSharedMemorySize, SCAN_SMEM);
        attr_done = true;
    }

    prep_kernel<<<dim3(HIDD, 2), HIDD>>>(W_ih, b_ih, b_hh);

    // layer 0
    xb_gemm<<<dim3(8, S_LEN), 256>>>(src, embed, 0);
    rnn_scan2<<<128, 256, SCAN_SMEM>>>(W_hh, 0, out);

    // layer 1 (input = layer-0 outputs in g_Y)
    xb_gemm<<<dim3(8, S_LEN), 256>>>(nullptr, embed, 1);
    rnn_scan2<<<128, 256, SCAN_SMEM>>>(W_hh, 1, out);
}